// round 12
// baseline (speedup 1.0000x reference)
#include <cuda_runtime.h>
#include <cuda_fp16.h>
#include <stdint.h>

#define NN 4096
#define THREADS 256
#define STAGES 3
#define BK 64
#define KT (NN / BK)   // 64 iterations
#define BM 128
#define BN 128
#define LDB 144  // bytes per smem row: 64 halves (128B) + 16B pad -> conflict-free ldmatrix

#define ASTG (BM * LDB)             // 18432 bytes per operand stage
#define STG (2 * ASTG)              // 36864 per stage (A+B)
#define SMEM_BAR (STAGES * STG)     // 110592: 6 mbarriers live here
#define SMEM_TOTAL (SMEM_BAR + 64)

// Scratch (device globals: no allocations).
__device__ __half g_Sh[(size_t)NN * NN];   // f16 logits, then probs in-place (32 MB)
__device__ __half g_Fh[(size_t)NN * NN];   // f16 feats (32 MB)

__device__ __forceinline__ uint32_t smem_u32(const void* p) {
    uint32_t a;
    asm("{ .reg .u64 t; cvta.to.shared.u64 t, %1; cvt.u32.u64 %0, t; }" : "=r"(a) : "l"(p));
    return a;
}

#define CP_ASYNC16(dst, src) \
    asm volatile("cp.async.cg.shared.global [%0], [%1], 16;" :: "r"(dst), "l"(src) : "memory")

#define MBAR_INIT(addr, cnt) \
    asm volatile("mbarrier.init.shared.b64 [%0], %1;" :: "r"(addr), "r"(cnt) : "memory")

#define MBAR_ARRIVE(addr) \
    asm volatile("mbarrier.arrive.shared.b64 _, [%0];" :: "r"(addr) : "memory")

// arrive (noinc) when ALL prior cp.async of this thread complete.
#define CP_ASYNC_MBAR_ARRIVE(addr) \
    asm volatile("cp.async.mbarrier.arrive.noinc.shared.b64 [%0];" :: "r"(addr) : "memory")

#define MBAR_WAIT(addr, ph) do {                                                     \
    uint32_t _m = (addr), _p = (uint32_t)(ph), _d;                                   \
    asm volatile("{ .reg .pred p; mbarrier.try_wait.parity.shared.b64 p, [%1], %2;"  \
                 " selp.b32 %0, 1, 0, p; }" : "=r"(_d) : "r"(_m), "r"(_p) : "memory");\
    while (!_d) {                                                                    \
        asm volatile("{ .reg .pred p; mbarrier.try_wait.parity.shared.b64 p, [%1], %2, 0x989680;" \
                     " selp.b32 %0, 1, 0, p; }" : "=r"(_d) : "r"(_m), "r"(_p) : "memory");        \
    }                                                                                \
} while (0)

#define LDSM_X4(r0, r1, r2, r3, addr)                                        \
    asm volatile("ldmatrix.sync.aligned.m8n8.x4.shared.b16 {%0,%1,%2,%3}, [%4];" \
                 : "=r"(r0), "=r"(r1), "=r"(r2), "=r"(r3) : "r"(addr))

#define MMA_F16(d, a, b0, b1)                                                \
    asm volatile(                                                            \
        "mma.sync.aligned.m16n8k16.row.col.f32.f16.f16.f32 "                 \
        "{%0,%1,%2,%3}, {%4,%5,%6,%7}, {%8,%9}, {%0,%1,%2,%3};"              \
        : "+f"((d)[0]), "+f"((d)[1]), "+f"((d)[2]), "+f"((d)[3])             \
        : "r"((a)[0]), "r"((a)[1]), "r"((a)[2]), "r"((a)[3]),                \
          "r"(b0), "r"(b1))

// NT GEMM, f16 inputs, fp32 accum, OT output: C[i][j] = scale*sum_k A[i][k]*B[j][k]
// 8 warps, 64x32 warp tiles; mbarrier-decoupled 3-stage cp.async pipeline.
// FREE barriers use warp-aggregated arrivals (count=8, lane 0 arrives).
template <typename OT>
__global__ __launch_bounds__(THREADS, 2) void gemm_nt_f16(const __half* __restrict__ A,
                                                          const __half* __restrict__ B,
                                                          OT* __restrict__ C, float scale) {
    extern __shared__ char smem[];
    const uint32_t sb = smem_u32(smem);
    const int tid = threadIdx.x;
    const int wid = tid >> 5;
    const int lane = tid & 31;
    const int q = lane >> 2, r = lane & 3;
    const int wm = wid & 1;   // 2 warp rows x 64
    const int wn = wid >> 1;  // 4 warp cols x 32
    const int rowBase = blockIdx.y * BM;
    const int colBase = blockIdx.x * BN;

#define FULLB(s) (sb + SMEM_BAR + (s) * 8)
#define FREEB(s) (sb + SMEM_BAR + 24 + (s) * 8)

    if (tid == 0) {
#pragma unroll
        for (int s = 0; s < STAGES; s++) {
            MBAR_INIT(FULLB(s), THREADS);  // per-thread cp.async completion arrivals
            MBAR_INIT(FREEB(s), 8);        // one arrival per warp (lane 0)
        }
    }
    __syncthreads();

    const int ldRow = tid >> 3;
    const int ldC = (tid & 7) * 16;
    const char* Ag = (const char*)A + ((size_t)(rowBase + ldRow) * NN) * 2 + ldC;
    const char* Bg = (const char*)B + ((size_t)(colBase + ldRow) * NN) * 2 + ldC;
    const size_t GROW = (size_t)32 * NN * 2;

    const int ml = lane >> 3;
    const int lrow = (ml & 1) * 8 + (lane & 7);
    const int lk = (ml >> 1) * 16;
    const uint32_t aoff = (uint32_t)((wm * 64 + lrow) * LDB + lk);
    const uint32_t boff = (uint32_t)(ASTG + (wn * 32 + lrow) * LDB + lk);

    float c[4][4][4];
#pragma unroll
    for (int i = 0; i < 4; i++)
#pragma unroll
        for (int j = 0; j < 4; j++)
#pragma unroll
            for (int e = 0; e < 4; e++) c[i][j][e] = 0.f;

#define LOADSTAGE(sidx)                                                            \
    do {                                                                           \
        const uint32_t s_b = sb + (sidx) * STG;                                    \
        _Pragma("unroll") for (int l = 0; l < 4; l++) {                            \
            CP_ASYNC16(s_b + (ldRow + l * 32) * LDB + ldC, Ag + l * GROW);         \
            CP_ASYNC16(s_b + ASTG + (ldRow + l * 32) * LDB + ldC, Bg + l * GROW);  \
        }                                                                          \
        CP_ASYNC_MBAR_ARRIVE(FULLB(sidx));                                         \
        Ag += 128;                                                                 \
        Bg += 128;                                                                 \
    } while (0)

#define COMPUTE(sidx)                                                              \
    do {                                                                           \
        const uint32_t abase = sb + (sidx) * STG + aoff;                           \
        const uint32_t bbase = sb + (sidx) * STG + boff;                           \
        uint32_t a[2][4][4], b[2][2][4];                                           \
        _Pragma("unroll") for (int im = 0; im < 4; im++)                           \
            LDSM_X4(a[0][im][0], a[0][im][1], a[0][im][2], a[0][im][3],            \
                    abase + im * (16 * LDB));                                      \
        _Pragma("unroll") for (int jn = 0; jn < 2; jn++)                           \
            LDSM_X4(b[0][jn][0], b[0][jn][1], b[0][jn][2], b[0][jn][3],            \
                    bbase + jn * (16 * LDB));                                      \
        _Pragma("unroll") for (int ks = 0; ks < 4; ks++) {                         \
            const int cur = ks & 1;                                                \
            if (ks < 3) {                                                          \
                _Pragma("unroll") for (int im = 0; im < 4; im++)                   \
                    LDSM_X4(a[cur ^ 1][im][0], a[cur ^ 1][im][1],                  \
                            a[cur ^ 1][im][2], a[cur ^ 1][im][3],                  \
                            abase + im * (16 * LDB) + (ks + 1) * 32);              \
                _Pragma("unroll") for (int jn = 0; jn < 2; jn++)                   \
                    LDSM_X4(b[cur ^ 1][jn][0], b[cur ^ 1][jn][1],                  \
                            b[cur ^ 1][jn][2], b[cur ^ 1][jn][3],                  \
                            bbase + jn * (16 * LDB) + (ks + 1) * 32);              \
            }                                                                      \
            _Pragma("unroll") for (int im = 0; im < 4; im++)                       \
                _Pragma("unroll") for (int in_ = 0; in_ < 4; in_++) {              \
                    const int jn = in_ >> 1, o = in_ & 1;                          \
                    MMA_F16(c[im][in_], a[cur][im], b[cur][jn][o], b[cur][jn][2 + o]); \
                }                                                                  \
        }                                                                          \
        if (lane == 0) MBAR_ARRIVE(FREEB(sidx));  /* last LDSM on stage was warp-collective */ \
    } while (0)

    // prologue: fill stages 0 and 1 (k-tiles 0, 1)
    LOADSTAGE(0);
    LOADSTAGE(1);

    // main loop unrolled by 3; kt = 3g + i, stage = kt % 3.
    int pg = 0;  // g & 1
    for (int g = 0; g < 21; g++) {
        // kt = 3g: compute stage 0; load kt+2 = 3g+2 -> stage 2
        MBAR_WAIT(FULLB(0), pg);
        COMPUTE(0);
        if (g > 0) MBAR_WAIT(FREEB(2), pg ^ 1);  // stage 2 consumed at idx g-1
        LOADSTAGE(2);
        // kt = 3g+1: compute stage 1; load 3g+3 -> stage 0 (freed at 3g, idx g)
        MBAR_WAIT(FULLB(1), pg);
        COMPUTE(1);
        MBAR_WAIT(FREEB(0), pg);
        LOADSTAGE(0);
        // kt = 3g+2: compute stage 2; load 3g+4 -> stage 1 (freed at 3g+1, idx g)
        MBAR_WAIT(FULLB(2), pg);
        COMPUTE(2);
        if (g < 20) {
            MBAR_WAIT(FREEB(1), pg);
            LOADSTAGE(1);
        }
        pg ^= 1;
    }
    // tail: kt = 63, stage 0, fill idx 21 -> parity 1 == pg
    MBAR_WAIT(FULLB(0), pg);
    COMPUTE(0);

    // epilogue
#pragma unroll
    for (int im = 0; im < 4; im++) {
        const int row0 = rowBase + wm * 64 + im * 16 + q;
#pragma unroll
        for (int in_ = 0; in_ < 4; in_++) {
            const int col = colBase + wn * 32 + in_ * 8 + 2 * r;
            if constexpr (sizeof(OT) == 4) {
                float2 v0 = make_float2(c[im][in_][0] * scale, c[im][in_][1] * scale);
                float2 v1 = make_float2(c[im][in_][2] * scale, c[im][in_][3] * scale);
                *reinterpret_cast<float2*>((float*)C + (size_t)row0 * NN + col) = v0;
                *reinterpret_cast<float2*>((float*)C + (size_t)(row0 + 8) * NN + col) = v1;
            } else {
                __half2 h0 = __floats2half2_rn(c[im][in_][0] * scale, c[im][in_][1] * scale);
                __half2 h1 = __floats2half2_rn(c[im][in_][2] * scale, c[im][in_][3] * scale);
                *reinterpret_cast<__half2*>((__half*)C + (size_t)row0 * NN + col) = h0;
                *reinterpret_cast<__half2*>((__half*)C + (size_t)(row0 + 8) * NN + col) = h1;
            }
        }
    }
}

// ---------------- prep: feats f32 -> f16 ----------------
__global__ __launch_bounds__(256) void prep_feats(const float* __restrict__ in,
                                                  __half* __restrict__ out) {
    size_t i = ((size_t)blockIdx.x * 256 + threadIdx.x) * 8;
    float4 v0 = *reinterpret_cast<const float4*>(in + i);
    float4 v1 = *reinterpret_cast<const float4*>(in + i + 4);
    __half2 h[4];
    h[0] = __floats2half2_rn(v0.x, v0.y);
    h[1] = __floats2half2_rn(v0.z, v0.w);
    h[2] = __floats2half2_rn(v1.x, v1.y);
    h[3] = __floats2half2_rn(v1.z, v1.w);
    *reinterpret_cast<uint4*>(out + i) = *reinterpret_cast<uint4*>(h);
}

// ---------------- row softmax on f16 logits, diag masked, f16 probs in-place ----------------
__global__ __launch_bounds__(256) void softmax_rows(__half* __restrict__ S) {
    __shared__ float row[NN];  // 16 KB
    __shared__ float red[256];
    const int ri = blockIdx.x;
    const int t = threadIdx.x;
    __half2* rp = reinterpret_cast<__half2*>(S + (size_t)ri * NN);

    for (int j = t; j < NN / 2; j += 256) {
        float2 v = __half22float2(rp[j]);
        row[2 * j] = v.x;
        row[2 * j + 1] = v.y;
    }
    __syncthreads();
    if (t == 0) row[ri] = -3.4e38f;  // mask diagonal
    __syncthreads();

    float m = -3.4e38f;
    for (int j = t; j < NN; j += 256) m = fmaxf(m, row[j]);
    red[t] = m;
    __syncthreads();
    for (int s = 128; s > 0; s >>= 1) {
        if (t < s) red[t] = fmaxf(red[t], red[t + s]);
        __syncthreads();
    }
    m = red[0];
    __syncthreads();

    float sum = 0.f;
    for (int j = t; j < NN; j += 256) {
        float e = __expf(row[j] - m);
        row[j] = e;
        sum += e;
    }
    red[t] = sum;
    __syncthreads();
    for (int s = 128; s > 0; s >>= 1) {
        if (t < s) red[t] += red[t + s];
        __syncthreads();
    }
    const float inv = 1.f / red[0];
    __syncthreads();

    for (int j = t; j < NN / 2; j += 256)
        rp[j] = __floats2half2_rn(row[2 * j] * inv, row[2 * j + 1] * inv);
}

extern "C" void kernel_launch(void* const* d_in, const int* in_sizes, int n_in,
                              void* d_out, int out_size) {
    const float* feats = (const float*)d_in[0];
    float* out = (float*)d_out;

    void *sp, *fp;
    cudaGetSymbolAddress(&sp, g_Sh);
    cudaGetSymbolAddress(&fp, g_Fh);
    __half* Sh = (__half*)sp;
    __half* Fh = (__half*)fp;

    cudaFuncSetAttribute(gemm_nt_f16<__half>, cudaFuncAttributeMaxDynamicSharedMemorySize,
                         SMEM_TOTAL);
    cudaFuncSetAttribute(gemm_nt_f16<float>, cudaFuncAttributeMaxDynamicSharedMemorySize,
                         SMEM_TOTAL);

    prep_feats<<<(NN * NN) / 2048, 256>>>(feats, Fh);

    dim3 grid(NN / BN, NN / BM);  // (32, 32)
    // S = Fh @ Fh^T / D  (f16 logits out)
    gemm_nt_f16<__half><<<grid, THREADS, SMEM_TOTAL>>>(Fh, Fh, Sh, 1.0f / (float)NN);
    // P = softmax(S), diag masked, in-place f16
    softmax_rows<<<NN, 256>>>(Sh);
    // out = P @ Fh^T / sqrt(D)  (fp32 out)
    gemm_nt_f16<float><<<grid, THREADS, SMEM_TOTAL>>>(Sh, Fh, out, 1.0f / 64.0f);
}

// round 13
// speedup vs baseline: 1.6004x; 1.6004x over previous
#include <cuda_runtime.h>
#include <cuda_fp16.h>
#include <stdint.h>

#define NN 4096
#define THREADS 256
#define STAGES 3
#define BK 64
#define KT (NN / BK)   // 64 iterations
#define BM 128
#define BN 128
#define LDB 144  // bytes per smem row: 64 halves (128B) + 16B pad -> conflict-free ldmatrix

#define ASTG (BM * LDB)             // 18432 bytes per operand stage
#define STG (2 * ASTG)              // 36864 per stage (A+B)
#define SMEM_BAR (STAGES * STG)     // 110592: 6 mbarriers live here
#define SMEM_TOTAL (SMEM_BAR + 64)
#define TSTRIDE 130                 // halves; 65 words -> bank stride 1 (conflict-free mirror reads)

// Scratch (device globals: no allocations).
__device__ __half g_Sh[(size_t)NN * NN];   // f16 logits, then probs in-place (32 MB)
__device__ __half g_Fh[(size_t)NN * NN];   // f16 feats (32 MB)

__device__ __forceinline__ uint32_t smem_u32(const void* p) {
    uint32_t a;
    asm("{ .reg .u64 t; cvta.to.shared.u64 t, %1; cvt.u32.u64 %0, t; }" : "=r"(a) : "l"(p));
    return a;
}

#define CP_ASYNC16(dst, src) \
    asm volatile("cp.async.cg.shared.global [%0], [%1], 16;" :: "r"(dst), "l"(src) : "memory")

#define MBAR_INIT(addr, cnt) \
    asm volatile("mbarrier.init.shared.b64 [%0], %1;" :: "r"(addr), "r"(cnt) : "memory")

#define MBAR_ARRIVE(addr) \
    asm volatile("mbarrier.arrive.shared.b64 _, [%0];" :: "r"(addr) : "memory")

// arrive (noinc) when ALL prior cp.async of this thread complete.
#define CP_ASYNC_MBAR_ARRIVE(addr) \
    asm volatile("cp.async.mbarrier.arrive.noinc.shared.b64 [%0];" :: "r"(addr) : "memory")

#define MBAR_WAIT(addr, ph) do {                                                     \
    uint32_t _m = (addr), _p = (uint32_t)(ph), _d;                                   \
    asm volatile("{ .reg .pred p; mbarrier.try_wait.parity.shared.b64 p, [%1], %2;"  \
                 " selp.b32 %0, 1, 0, p; }" : "=r"(_d) : "r"(_m), "r"(_p) : "memory");\
    while (!_d) {                                                                    \
        asm volatile("{ .reg .pred p; mbarrier.try_wait.parity.shared.b64 p, [%1], %2, 0x989680;" \
                     " selp.b32 %0, 1, 0, p; }" : "=r"(_d) : "r"(_m), "r"(_p) : "memory");        \
    }                                                                                \
} while (0)

#define LDSM_X4(r0, r1, r2, r3, addr)                                        \
    asm volatile("ldmatrix.sync.aligned.m8n8.x4.shared.b16 {%0,%1,%2,%3}, [%4];" \
                 : "=r"(r0), "=r"(r1), "=r"(r2), "=r"(r3) : "r"(addr))

#define MMA_F16(d, a, b0, b1)                                                \
    asm volatile(                                                            \
        "mma.sync.aligned.m16n8k16.row.col.f32.f16.f16.f32 "                 \
        "{%0,%1,%2,%3}, {%4,%5,%6,%7}, {%8,%9}, {%0,%1,%2,%3};"              \
        : "+f"((d)[0]), "+f"((d)[1]), "+f"((d)[2]), "+f"((d)[3])             \
        : "r"((a)[0]), "r"((a)[1]), "r"((a)[2]), "r"((a)[3]),                \
          "r"(b0), "r"(b1))

// NT GEMM, f16 inputs, fp32 accum, OT output: C[i][j] = scale*sum_k A[i][k]*B[j][k]
// 8 warps, 64x32 warp tiles; mbarrier-decoupled 3-stage cp.async pipeline (R10 base).
// SYM: output is symmetric (A==B); compute only upper-triangle tiles and mirror.
template <typename OT, bool SYM>
__global__ __launch_bounds__(THREADS, 2) void gemm_nt_f16(const __half* __restrict__ A,
                                                          const __half* __restrict__ B,
                                                          OT* __restrict__ C, float scale) {
    if constexpr (SYM) {
        if (blockIdx.y > blockIdx.x) return;  // lower triangle handled by mirror
    }
    extern __shared__ char smem[];
    const uint32_t sb = smem_u32(smem);
    const int tid = threadIdx.x;
    const int wid = tid >> 5;
    const int lane = tid & 31;
    const int q = lane >> 2, r = lane & 3;
    const int wm = wid & 1;   // 2 warp rows x 64
    const int wn = wid >> 1;  // 4 warp cols x 32
    const int rowBase = blockIdx.y * BM;
    const int colBase = blockIdx.x * BN;

#define FULLB(s) (sb + SMEM_BAR + (s) * 8)
#define FREEB(s) (sb + SMEM_BAR + 24 + (s) * 8)

    if (tid == 0) {
#pragma unroll
        for (int s = 0; s < STAGES; s++) {
            MBAR_INIT(FULLB(s), THREADS);
            MBAR_INIT(FREEB(s), THREADS);
        }
    }
    __syncthreads();

    const int ldRow = tid >> 3;
    const int ldC = (tid & 7) * 16;
    const char* Ag = (const char*)A + ((size_t)(rowBase + ldRow) * NN) * 2 + ldC;
    const char* Bg = (const char*)B + ((size_t)(colBase + ldRow) * NN) * 2 + ldC;
    const size_t GROW = (size_t)32 * NN * 2;

    const int ml = lane >> 3;
    const int lrow = (ml & 1) * 8 + (lane & 7);
    const int lk = (ml >> 1) * 16;
    const uint32_t aoff = (uint32_t)((wm * 64 + lrow) * LDB + lk);
    const uint32_t boff = (uint32_t)(ASTG + (wn * 32 + lrow) * LDB + lk);

    float c[4][4][4];
#pragma unroll
    for (int i = 0; i < 4; i++)
#pragma unroll
        for (int j = 0; j < 4; j++)
#pragma unroll
            for (int e = 0; e < 4; e++) c[i][j][e] = 0.f;

#define LOADSTAGE(sidx)                                                            \
    do {                                                                           \
        const uint32_t s_b = sb + (sidx) * STG;                                    \
        _Pragma("unroll") for (int l = 0; l < 4; l++) {                            \
            CP_ASYNC16(s_b + (ldRow + l * 32) * LDB + ldC, Ag + l * GROW);         \
            CP_ASYNC16(s_b + ASTG + (ldRow + l * 32) * LDB + ldC, Bg + l * GROW);  \
        }                                                                          \
        CP_ASYNC_MBAR_ARRIVE(FULLB(sidx));                                         \
        Ag += 128;                                                                 \
        Bg += 128;                                                                 \
    } while (0)

#define COMPUTE(sidx)                                                              \
    do {                                                                           \
        const uint32_t abase = sb + (sidx) * STG + aoff;                           \
        const uint32_t bbase = sb + (sidx) * STG + boff;                           \
        uint32_t a[2][4][4], b[2][2][4];                                           \
        _Pragma("unroll") for (int im = 0; im < 4; im++)                           \
            LDSM_X4(a[0][im][0], a[0][im][1], a[0][im][2], a[0][im][3],            \
                    abase + im * (16 * LDB));                                      \
        _Pragma("unroll") for (int jn = 0; jn < 2; jn++)                           \
            LDSM_X4(b[0][jn][0], b[0][jn][1], b[0][jn][2], b[0][jn][3],            \
                    bbase + jn * (16 * LDB));                                      \
        _Pragma("unroll") for (int ks = 0; ks < 4; ks++) {                         \
            const int cur = ks & 1;                                                \
            if (ks < 3) {                                                          \
                _Pragma("unroll") for (int im = 0; im < 4; im++)                   \
                    LDSM_X4(a[cur ^ 1][im][0], a[cur ^ 1][im][1],                  \
                            a[cur ^ 1][im][2], a[cur ^ 1][im][3],                  \
                            abase + im * (16 * LDB) + (ks + 1) * 32);              \
                _Pragma("unroll") for (int jn = 0; jn < 2; jn++)                   \
                    LDSM_X4(b[cur ^ 1][jn][0], b[cur ^ 1][jn][1],                  \
                            b[cur ^ 1][jn][2], b[cur ^ 1][jn][3],                  \
                            bbase + jn * (16 * LDB) + (ks + 1) * 32);              \
            }                                                                      \
            _Pragma("unroll") for (int im = 0; im < 4; im++)                       \
                _Pragma("unroll") for (int in_ = 0; in_ < 4; in_++) {              \
                    const int jn = in_ >> 1, o = in_ & 1;                          \
                    MMA_F16(c[im][in_], a[cur][im], b[cur][jn][o], b[cur][jn][2 + o]); \
                }                                                                  \
        }                                                                          \
        MBAR_ARRIVE(FREEB(sidx));                                                  \
    } while (0)

    LOADSTAGE(0);
    LOADSTAGE(1);

    int pg = 0;
    for (int g = 0; g < 21; g++) {
        MBAR_WAIT(FULLB(0), pg);
        COMPUTE(0);
        if (g > 0) MBAR_WAIT(FREEB(2), pg ^ 1);
        LOADSTAGE(2);
        MBAR_WAIT(FULLB(1), pg);
        COMPUTE(1);
        MBAR_WAIT(FREEB(0), pg);
        LOADSTAGE(0);
        MBAR_WAIT(FULLB(2), pg);
        COMPUTE(2);
        if (g < 20) {
            MBAR_WAIT(FREEB(1), pg);
            LOADSTAGE(1);
        }
        pg ^= 1;
    }
    MBAR_WAIT(FULLB(0), pg);
    COMPUTE(0);

    // epilogue: direct write of this tile
#pragma unroll
    for (int im = 0; im < 4; im++) {
        const int row0 = rowBase + wm * 64 + im * 16 + q;
#pragma unroll
        for (int in_ = 0; in_ < 4; in_++) {
            const int col = colBase + wn * 32 + in_ * 8 + 2 * r;
            if constexpr (sizeof(OT) == 4) {
                float2 v0 = make_float2(c[im][in_][0] * scale, c[im][in_][1] * scale);
                float2 v1 = make_float2(c[im][in_][2] * scale, c[im][in_][3] * scale);
                *reinterpret_cast<float2*>((float*)C + (size_t)row0 * NN + col) = v0;
                *reinterpret_cast<float2*>((float*)C + (size_t)(row0 + 8) * NN + col) = v1;
            } else {
                __half2 h0 = __floats2half2_rn(c[im][in_][0] * scale, c[im][in_][1] * scale);
                __half2 h1 = __floats2half2_rn(c[im][in_][2] * scale, c[im][in_][3] * scale);
                *reinterpret_cast<__half2*>((__half*)C + (size_t)row0 * NN + col) = h0;
                *reinterpret_cast<__half2*>((__half*)C + (size_t)(row0 + 8) * NN + col) = h1;
            }
        }
    }

    // mirror epilogue: write the transposed tile to C[colBase..][rowBase..]
    if constexpr (SYM) {
        if (blockIdx.y != blockIdx.x) {
            __syncthreads();  // pipeline smem no longer needed; reuse as transpose buffer
            __half* T = reinterpret_cast<__half*>(smem);
            // stage this tile into smem (normal orientation, f16, stride 130)
#pragma unroll
            for (int im = 0; im < 4; im++) {
                const int rl = wm * 64 + im * 16 + q;
#pragma unroll
                for (int in_ = 0; in_ < 4; in_++) {
                    const int cl = wn * 32 + in_ * 8 + 2 * r;
                    __half2 h0 = __floats2half2_rn(c[im][in_][0] * scale, c[im][in_][1] * scale);
                    __half2 h1 = __floats2half2_rn(c[im][in_][2] * scale, c[im][in_][3] * scale);
                    *reinterpret_cast<__half2*>(T + rl * TSTRIDE + cl) = h0;
                    *reinterpret_cast<__half2*>(T + (rl + 8) * TSTRIDE + cl) = h1;
                }
            }
            __syncthreads();
            // transposed write: out(r_t, c_t) = T[c_t][r_t]
            // warp handles one output row per iter; lane covers cols {lane, lane+32, lane+64, lane+96}
            __half* Cb = (__half*)C + (size_t)colBase * NN + rowBase;
#pragma unroll
            for (int it = 0; it < 16; it++) {
                const int r_t = it * 8 + wid;
                __half* dst = Cb + (size_t)r_t * NN;
#pragma unroll
                for (int j = 0; j < 4; j++) {
                    const int c_t = lane + 32 * j;
                    dst[c_t] = T[c_t * TSTRIDE + r_t];  // conflict-free: bank = lane
                }
            }
        }
    }
}

// ---------------- prep: feats f32 -> f16 ----------------
__global__ __launch_bounds__(256) void prep_feats(const float* __restrict__ in,
                                                  __half* __restrict__ out) {
    size_t i = ((size_t)blockIdx.x * 256 + threadIdx.x) * 8;
    float4 v0 = *reinterpret_cast<const float4*>(in + i);
    float4 v1 = *reinterpret_cast<const float4*>(in + i + 4);
    __half2 h[4];
    h[0] = __floats2half2_rn(v0.x, v0.y);
    h[1] = __floats2half2_rn(v0.z, v0.w);
    h[2] = __floats2half2_rn(v1.x, v1.y);
    h[3] = __floats2half2_rn(v1.z, v1.w);
    *reinterpret_cast<uint4*>(out + i) = *reinterpret_cast<uint4*>(h);
}

// ---------------- row softmax on f16 logits, diag masked, f16 probs in-place ----------------
__global__ __launch_bounds__(256) void softmax_rows(__half* __restrict__ S) {
    __shared__ float row[NN];  // 16 KB
    __shared__ float red[256];
    const int ri = blockIdx.x;
    const int t = threadIdx.x;
    __half2* rp = reinterpret_cast<__half2*>(S + (size_t)ri * NN);

    for (int j = t; j < NN / 2; j += 256) {
        float2 v = __half22float2(rp[j]);
        row[2 * j] = v.x;
        row[2 * j + 1] = v.y;
    }
    __syncthreads();
    if (t == 0) row[ri] = -3.4e38f;  // mask diagonal
    __syncthreads();

    float m = -3.4e38f;
    for (int j = t; j < NN; j += 256) m = fmaxf(m, row[j]);
    red[t] = m;
    __syncthreads();
    for (int s = 128; s > 0; s >>= 1) {
        if (t < s) red[t] = fmaxf(red[t], red[t + s]);
        __syncthreads();
    }
    m = red[0];
    __syncthreads();

    float sum = 0.f;
    for (int j = t; j < NN; j += 256) {
        float e = __expf(row[j] - m);
        row[j] = e;
        sum += e;
    }
    red[t] = sum;
    __syncthreads();
    for (int s = 128; s > 0; s >>= 1) {
        if (t < s) red[t] += red[t + s];
        __syncthreads();
    }
    const float inv = 1.f / red[0];
    __syncthreads();

    for (int j = t; j < NN / 2; j += 256)
        rp[j] = __floats2half2_rn(row[2 * j] * inv, row[2 * j + 1] * inv);
}

extern "C" void kernel_launch(void* const* d_in, const int* in_sizes, int n_in,
                              void* d_out, int out_size) {
    const float* feats = (const float*)d_in[0];
    float* out = (float*)d_out;

    void *sp, *fp;
    cudaGetSymbolAddress(&sp, g_Sh);
    cudaGetSymbolAddress(&fp, g_Fh);
    __half* Sh = (__half*)sp;
    __half* Fh = (__half*)fp;

    cudaFuncSetAttribute((const void*)gemm_nt_f16<__half, true>,
                         cudaFuncAttributeMaxDynamicSharedMemorySize, SMEM_TOTAL);
    cudaFuncSetAttribute((const void*)gemm_nt_f16<float, false>,
                         cudaFuncAttributeMaxDynamicSharedMemorySize, SMEM_TOTAL);

    prep_feats<<<(NN * NN) / 2048, 256>>>(feats, Fh);

    dim3 grid(NN / BN, NN / BM);  // (32, 32)
    // S = Fh @ Fh^T / D  (symmetric: upper triangle computed, mirrored)
    gemm_nt_f16<__half, true><<<grid, THREADS, SMEM_TOTAL>>>(Fh, Fh, Sh, 1.0f / (float)NN);
    // P = softmax(S), diag masked, in-place f16
    softmax_rows<<<NN, 256>>>(Sh);
    // out = P @ Fh^T / sqrt(D)  (fp32 out)
    gemm_nt_f16<float, false><<<grid, THREADS, SMEM_TOTAL>>>(Sh, Fh, out, 1.0f / 64.0f);
}

// round 14
// speedup vs baseline: 1.6387x; 1.0240x over previous
#include <cuda_runtime.h>
#include <cuda_fp16.h>
#include <stdint.h>

#define NN 4096
#define THREADS 256
#define STAGES 3
#define BK 64
#define KT (NN / BK)   // 64 iterations
#define BM 128
#define BN 128
#define NTILE 32       // NN / BM
#define NTRI (NTILE * (NTILE + 1) / 2)  // 528 upper-triangle tiles
#define LDB 144  // bytes per smem row: 64 halves (128B) + 16B pad -> conflict-free ldmatrix

#define ASTG (BM * LDB)             // 18432 bytes per operand stage
#define STG (2 * ASTG)              // 36864 per stage (A+B)
#define SMEM_BAR (STAGES * STG)     // 110592: 6 mbarriers live here
#define SMEM_TOTAL (SMEM_BAR + 64)
#define TSTRIDE 130                 // halves; 65 words -> bank stride 1 (conflict-free mirror reads)

// Scratch (device globals: no allocations).
__device__ __half g_Sh[(size_t)NN * NN];   // f16 logits, then probs in-place (32 MB)
__device__ __half g_Fh[(size_t)NN * NN];   // f16 feats (32 MB)

__device__ __forceinline__ uint32_t smem_u32(const void* p) {
    uint32_t a;
    asm("{ .reg .u64 t; cvta.to.shared.u64 t, %1; cvt.u32.u64 %0, t; }" : "=r"(a) : "l"(p));
    return a;
}

#define CP_ASYNC16(dst, src) \
    asm volatile("cp.async.cg.shared.global [%0], [%1], 16;" :: "r"(dst), "l"(src) : "memory")

#define MBAR_INIT(addr, cnt) \
    asm volatile("mbarrier.init.shared.b64 [%0], %1;" :: "r"(addr), "r"(cnt) : "memory")

#define MBAR_ARRIVE(addr) \
    asm volatile("mbarrier.arrive.shared.b64 _, [%0];" :: "r"(addr) : "memory")

// arrive (noinc) when ALL prior cp.async of this thread complete.
#define CP_ASYNC_MBAR_ARRIVE(addr) \
    asm volatile("cp.async.mbarrier.arrive.noinc.shared.b64 [%0];" :: "r"(addr) : "memory")

#define MBAR_WAIT(addr, ph) do {                                                     \
    uint32_t _m = (addr), _p = (uint32_t)(ph), _d;                                   \
    asm volatile("{ .reg .pred p; mbarrier.try_wait.parity.shared.b64 p, [%1], %2;"  \
                 " selp.b32 %0, 1, 0, p; }" : "=r"(_d) : "r"(_m), "r"(_p) : "memory");\
    while (!_d) {                                                                    \
        asm volatile("{ .reg .pred p; mbarrier.try_wait.parity.shared.b64 p, [%1], %2, 0x989680;" \
                     " selp.b32 %0, 1, 0, p; }" : "=r"(_d) : "r"(_m), "r"(_p) : "memory");        \
    }                                                                                \
} while (0)

#define LDSM_X4(r0, r1, r2, r3, addr)                                        \
    asm volatile("ldmatrix.sync.aligned.m8n8.x4.shared.b16 {%0,%1,%2,%3}, [%4];" \
                 : "=r"(r0), "=r"(r1), "=r"(r2), "=r"(r3) : "r"(addr))

#define MMA_F16(d, a, b0, b1)                                                \
    asm volatile(                                                            \
        "mma.sync.aligned.m16n8k16.row.col.f32.f16.f16.f32 "                 \
        "{%0,%1,%2,%3}, {%4,%5,%6,%7}, {%8,%9}, {%0,%1,%2,%3};"              \
        : "+f"((d)[0]), "+f"((d)[1]), "+f"((d)[2]), "+f"((d)[3])             \
        : "r"((a)[0]), "r"((a)[1]), "r"((a)[2]), "r"((a)[3]),                \
          "r"(b0), "r"(b1))

// NT GEMM, f16 inputs, fp32 accum, OT output: C[i][j] = scale*sum_k A[i][k]*B[j][k]
// 8 warps, 64x32 warp tiles; mbarrier-decoupled 3-stage cp.async pipeline (R10 base).
// SYM: output symmetric (A==B); dense 1-D grid over the 528 upper-triangle tiles + mirror.
template <typename OT, bool SYM>
__global__ __launch_bounds__(THREADS, 2) void gemm_nt_f16(const __half* __restrict__ A,
                                                          const __half* __restrict__ B,
                                                          OT* __restrict__ C, float scale) {
    int bx, by;
    if constexpr (SYM) {
        // decode linear upper-triangle index (row-major: row i has NTILE-i tiles)
        int t = blockIdx.x;
        by = 0;
        while (t >= NTILE - by) {
            t -= NTILE - by;
            by++;
        }
        bx = by + t;
    } else {
        bx = blockIdx.x;
        by = blockIdx.y;
    }
    extern __shared__ char smem[];
    const uint32_t sb = smem_u32(smem);
    const int tid = threadIdx.x;
    const int wid = tid >> 5;
    const int lane = tid & 31;
    const int q = lane >> 2, r = lane & 3;
    const int wm = wid & 1;   // 2 warp rows x 64
    const int wn = wid >> 1;  // 4 warp cols x 32
    const int rowBase = by * BM;
    const int colBase = bx * BN;

#define FULLB(s) (sb + SMEM_BAR + (s) * 8)
#define FREEB(s) (sb + SMEM_BAR + 24 + (s) * 8)

    if (tid == 0) {
#pragma unroll
        for (int s = 0; s < STAGES; s++) {
            MBAR_INIT(FULLB(s), THREADS);
            MBAR_INIT(FREEB(s), THREADS);
        }
    }
    __syncthreads();

    const int ldRow = tid >> 3;
    const int ldC = (tid & 7) * 16;
    const char* Ag = (const char*)A + ((size_t)(rowBase + ldRow) * NN) * 2 + ldC;
    const char* Bg = (const char*)B + ((size_t)(colBase + ldRow) * NN) * 2 + ldC;
    const size_t GROW = (size_t)32 * NN * 2;

    const int ml = lane >> 3;
    const int lrow = (ml & 1) * 8 + (lane & 7);
    const int lk = (ml >> 1) * 16;
    const uint32_t aoff = (uint32_t)((wm * 64 + lrow) * LDB + lk);
    const uint32_t boff = (uint32_t)(ASTG + (wn * 32 + lrow) * LDB + lk);

    float c[4][4][4];
#pragma unroll
    for (int i = 0; i < 4; i++)
#pragma unroll
        for (int j = 0; j < 4; j++)
#pragma unroll
            for (int e = 0; e < 4; e++) c[i][j][e] = 0.f;

#define LOADSTAGE(sidx)                                                            \
    do {                                                                           \
        const uint32_t s_b = sb + (sidx) * STG;                                    \
        _Pragma("unroll") for (int l = 0; l < 4; l++) {                            \
            CP_ASYNC16(s_b + (ldRow + l * 32) * LDB + ldC, Ag + l * GROW);         \
            CP_ASYNC16(s_b + ASTG + (ldRow + l * 32) * LDB + ldC, Bg + l * GROW);  \
        }                                                                          \
        CP_ASYNC_MBAR_ARRIVE(FULLB(sidx));                                         \
        Ag += 128;                                                                 \
        Bg += 128;                                                                 \
    } while (0)

#define COMPUTE(sidx)                                                              \
    do {                                                                           \
        const uint32_t abase = sb + (sidx) * STG + aoff;                           \
        const uint32_t bbase = sb + (sidx) * STG + boff;                           \
        uint32_t a[2][4][4], b[2][2][4];                                           \
        _Pragma("unroll") for (int im = 0; im < 4; im++)                           \
            LDSM_X4(a[0][im][0], a[0][im][1], a[0][im][2], a[0][im][3],            \
                    abase + im * (16 * LDB));                                      \
        _Pragma("unroll") for (int jn = 0; jn < 2; jn++)                           \
            LDSM_X4(b[0][jn][0], b[0][jn][1], b[0][jn][2], b[0][jn][3],            \
                    bbase + jn * (16 * LDB));                                      \
        _Pragma("unroll") for (int ks = 0; ks < 4; ks++) {                         \
            const int cur = ks & 1;                                                \
            if (ks < 3) {                                                          \
                _Pragma("unroll") for (int im = 0; im < 4; im++)                   \
                    LDSM_X4(a[cur ^ 1][im][0], a[cur ^ 1][im][1],                  \
                            a[cur ^ 1][im][2], a[cur ^ 1][im][3],                  \
                            abase + im * (16 * LDB) + (ks + 1) * 32);              \
                _Pragma("unroll") for (int jn = 0; jn < 2; jn++)                   \
                    LDSM_X4(b[cur ^ 1][jn][0], b[cur ^ 1][jn][1],                  \
                            b[cur ^ 1][jn][2], b[cur ^ 1][jn][3],                  \
                            bbase + jn * (16 * LDB) + (ks + 1) * 32);              \
            }                                                                      \
            _Pragma("unroll") for (int im = 0; im < 4; im++)                       \
                _Pragma("unroll") for (int in_ = 0; in_ < 4; in_++) {              \
                    const int jn = in_ >> 1, o = in_ & 1;                          \
                    MMA_F16(c[im][in_], a[cur][im], b[cur][jn][o], b[cur][jn][2 + o]); \
                }                                                                  \
        }                                                                          \
        MBAR_ARRIVE(FREEB(sidx));                                                  \
    } while (0)

    LOADSTAGE(0);
    LOADSTAGE(1);

    int pg = 0;
    for (int g = 0; g < 21; g++) {
        MBAR_WAIT(FULLB(0), pg);
        COMPUTE(0);
        if (g > 0) MBAR_WAIT(FREEB(2), pg ^ 1);
        LOADSTAGE(2);
        MBAR_WAIT(FULLB(1), pg);
        COMPUTE(1);
        MBAR_WAIT(FREEB(0), pg);
        LOADSTAGE(0);
        MBAR_WAIT(FULLB(2), pg);
        COMPUTE(2);
        if (g < 20) {
            MBAR_WAIT(FREEB(1), pg);
            LOADSTAGE(1);
        }
        pg ^= 1;
    }
    MBAR_WAIT(FULLB(0), pg);
    COMPUTE(0);

    // epilogue: direct write of this tile
#pragma unroll
    for (int im = 0; im < 4; im++) {
        const int row0 = rowBase + wm * 64 + im * 16 + q;
#pragma unroll
        for (int in_ = 0; in_ < 4; in_++) {
            const int col = colBase + wn * 32 + in_ * 8 + 2 * r;
            if constexpr (sizeof(OT) == 4) {
                float2 v0 = make_float2(c[im][in_][0] * scale, c[im][in_][1] * scale);
                float2 v1 = make_float2(c[im][in_][2] * scale, c[im][in_][3] * scale);
                *reinterpret_cast<float2*>((float*)C + (size_t)row0 * NN + col) = v0;
                *reinterpret_cast<float2*>((float*)C + (size_t)(row0 + 8) * NN + col) = v1;
            } else {
                __half2 h0 = __floats2half2_rn(c[im][in_][0] * scale, c[im][in_][1] * scale);
                __half2 h1 = __floats2half2_rn(c[im][in_][2] * scale, c[im][in_][3] * scale);
                *reinterpret_cast<__half2*>((__half*)C + (size_t)row0 * NN + col) = h0;
                *reinterpret_cast<__half2*>((__half*)C + (size_t)(row0 + 8) * NN + col) = h1;
            }
        }
    }

    // mirror epilogue: write the transposed tile to C[colBase..][rowBase..]
    if constexpr (SYM) {
        if (by != bx) {
            __syncthreads();  // pipeline smem no longer needed; reuse as transpose buffer
            __half* T = reinterpret_cast<__half*>(smem);
#pragma unroll
            for (int im = 0; im < 4; im++) {
                const int rl = wm * 64 + im * 16 + q;
#pragma unroll
                for (int in_ = 0; in_ < 4; in_++) {
                    const int cl = wn * 32 + in_ * 8 + 2 * r;
                    __half2 h0 = __floats2half2_rn(c[im][in_][0] * scale, c[im][in_][1] * scale);
                    __half2 h1 = __floats2half2_rn(c[im][in_][2] * scale, c[im][in_][3] * scale);
                    *reinterpret_cast<__half2*>(T + rl * TSTRIDE + cl) = h0;
                    *reinterpret_cast<__half2*>(T + (rl + 8) * TSTRIDE + cl) = h1;
                }
            }
            __syncthreads();
            __half* Cb = (__half*)C + (size_t)colBase * NN + rowBase;
#pragma unroll
            for (int it = 0; it < 16; it++) {
                const int r_t = it * 8 + wid;
                __half* dst = Cb + (size_t)r_t * NN;
#pragma unroll
                for (int j = 0; j < 4; j++) {
                    const int c_t = lane + 32 * j;
                    dst[c_t] = T[c_t * TSTRIDE + r_t];  // conflict-free: bank = lane
                }
            }
        }
    }
}

// ---------------- prep: feats f32 -> f16 ----------------
__global__ __launch_bounds__(256) void prep_feats(const float* __restrict__ in,
                                                  __half* __restrict__ out) {
    size_t i = ((size_t)blockIdx.x * 256 + threadIdx.x) * 8;
    float4 v0 = *reinterpret_cast<const float4*>(in + i);
    float4 v1 = *reinterpret_cast<const float4*>(in + i + 4);
    __half2 h[4];
    h[0] = __floats2half2_rn(v0.x, v0.y);
    h[1] = __floats2half2_rn(v0.z, v0.w);
    h[2] = __floats2half2_rn(v1.x, v1.y);
    h[3] = __floats2half2_rn(v1.z, v1.w);
    *reinterpret_cast<uint4*>(out + i) = *reinterpret_cast<uint4*>(h);
}

// ---------------- row softmax, register-resident, diag masked, f16 in-place ----------------
// 256 threads/row; thread t holds elems [8t,8t+8) and [2048+8t,2048+8t+8) in registers.
__global__ __launch_bounds__(256) void softmax_rows(__half* __restrict__ S) {
    __shared__ float red[8];
    const int ri = blockIdx.x;
    const int t = threadIdx.x;
    const int wid = t >> 5, lane = t & 31;
    uint4* rp = reinterpret_cast<uint4*>(S + (size_t)ri * NN);

    uint4 v0 = rp[t];
    uint4 v1 = rp[t + 256];
    float val[16];
    {
        const __half2* h0 = reinterpret_cast<const __half2*>(&v0);
        const __half2* h1 = reinterpret_cast<const __half2*>(&v1);
#pragma unroll
        for (int k = 0; k < 4; k++) {
            float2 f0 = __half22float2(h0[k]);
            float2 f1 = __half22float2(h1[k]);
            val[2 * k] = f0.x;
            val[2 * k + 1] = f0.y;
            val[8 + 2 * k] = f1.x;
            val[8 + 2 * k + 1] = f1.y;
        }
    }
    // mask diagonal element if it falls in this thread's ranges
    const int b0 = 8 * t, b1 = 2048 + 8 * t;
    if (ri >= b0 && ri < b0 + 8) val[ri - b0] = -3.4e38f;
    if (ri >= b1 && ri < b1 + 8) val[8 + ri - b1] = -3.4e38f;

    // block max
    float m = val[0];
#pragma unroll
    for (int k = 1; k < 16; k++) m = fmaxf(m, val[k]);
#pragma unroll
    for (int o = 16; o > 0; o >>= 1) m = fmaxf(m, __shfl_xor_sync(0xFFFFFFFF, m, o));
    if (lane == 0) red[wid] = m;
    __syncthreads();
    {
        float x = red[lane & 7];
#pragma unroll
        for (int o = 4; o > 0; o >>= 1) x = fmaxf(x, __shfl_xor_sync(0xFFFFFFFF, x, o));
        m = x;
    }
    __syncthreads();

    // exp + block sum
    float e[16];
    float s = 0.f;
#pragma unroll
    for (int k = 0; k < 16; k++) {
        e[k] = __expf(val[k] - m);  // diag -> exp(-huge) = 0
        s += e[k];
    }
#pragma unroll
    for (int o = 16; o > 0; o >>= 1) s += __shfl_xor_sync(0xFFFFFFFF, s, o);
    if (lane == 0) red[wid] = s;
    __syncthreads();
    {
        float x = red[lane & 7];
#pragma unroll
        for (int o = 4; o > 0; o >>= 1) x += __shfl_xor_sync(0xFFFFFFFF, x, o);
        s = x;
    }
    const float inv = 1.f / s;

    // pack + store
    {
        __half2* h0 = reinterpret_cast<__half2*>(&v0);
        __half2* h1 = reinterpret_cast<__half2*>(&v1);
#pragma unroll
        for (int k = 0; k < 4; k++) {
            h0[k] = __floats2half2_rn(e[2 * k] * inv, e[2 * k + 1] * inv);
            h1[k] = __floats2half2_rn(e[8 + 2 * k] * inv, e[8 + 2 * k + 1] * inv);
        }
    }
    rp[t] = v0;
    rp[t + 256] = v1;
}

extern "C" void kernel_launch(void* const* d_in, const int* in_sizes, int n_in,
                              void* d_out, int out_size) {
    const float* feats = (const float*)d_in[0];
    float* out = (float*)d_out;

    void *sp, *fp;
    cudaGetSymbolAddress(&sp, g_Sh);
    cudaGetSymbolAddress(&fp, g_Fh);
    __half* Sh = (__half*)sp;
    __half* Fh = (__half*)fp;

    cudaFuncSetAttribute((const void*)gemm_nt_f16<__half, true>,
                         cudaFuncAttributeMaxDynamicSharedMemorySize, SMEM_TOTAL);
    cudaFuncSetAttribute((const void*)gemm_nt_f16<float, false>,
                         cudaFuncAttributeMaxDynamicSharedMemorySize, SMEM_TOTAL);

    prep_feats<<<(NN * NN) / 2048, 256>>>(feats, Fh);

    // S = Fh @ Fh^T / D  (dense 1-D grid over 528 upper-triangle tiles, mirrored)
    gemm_nt_f16<__half, true><<<NTRI, THREADS, SMEM_TOTAL>>>(Fh, Fh, Sh, 1.0f / (float)NN);
    // P = softmax(S), diag masked, in-place f16
    softmax_rows<<<NN, 256>>>(Sh);
    // out = P @ Fh^T / sqrt(D)  (fp32 out)
    dim3 grid2(NN / BN, NN / BM);  // (32, 32)
    gemm_nt_f16<float, false><<<grid2, THREADS, SMEM_TOTAL>>>(Sh, Fh, out, 1.0f / 64.0f);
}

// round 15
// speedup vs baseline: 1.7194x; 1.0492x over previous
#include <cuda_runtime.h>
#include <cuda_fp16.h>
#include <stdint.h>

#define NN 4096
#define STAGES 3
#define BK 64
#define KT (NN / BK)   // 64 iterations
#define LDB 144        // bytes per smem row: 64 halves + 16B pad (conflict-free ldmatrix)

// ---- GEMM2 (fp32 accum, 128x128 CTA, 256 thr) ----
#define THREADS 256
#define BM 128
#define BN 128
#define ASTG (BM * LDB)             // 18432
#define STG (2 * ASTG)              // 36864
#define SMEM_BAR (STAGES * STG)     // 110592
#define SMEM_TOTAL (SMEM_BAR + 64)
#define TSTRIDE 130

// ---- GEMM1 (f16 accum, 256x256 CTA, 512 thr, symmetric triangle) ----
#define THR1 512
#define BM1 256
#define NTILE1 16                       // NN / BM1
#define NTRI1 (NTILE1 * (NTILE1 + 1) / 2)  // 136 tiles -> single wave on 148 SMs
#define ASTG1 (BM1 * LDB)               // 36864
#define STG1 (2 * ASTG1)                // 73728
#define SMEM1_BAR (STAGES * STG1)       // 221184
#define SMEM1_TOTAL (SMEM1_BAR + 64)
#define TS1 258                         // 256 halves + 2 pad: 129 words (==1 mod 32)

// Scratch (device globals: no allocations).
__device__ __half g_Sh[(size_t)NN * NN];   // f16 logits, then probs in-place (32 MB)
__device__ __half g_Fh[(size_t)NN * NN];   // f16 feats/64 (32 MB)

__device__ __forceinline__ uint32_t smem_u32(const void* p) {
    uint32_t a;
    asm("{ .reg .u64 t; cvta.to.shared.u64 t, %1; cvt.u32.u64 %0, t; }" : "=r"(a) : "l"(p));
    return a;
}

#define CP_ASYNC16(dst, src) \
    asm volatile("cp.async.cg.shared.global [%0], [%1], 16;" :: "r"(dst), "l"(src) : "memory")

#define MBAR_INIT(addr, cnt) \
    asm volatile("mbarrier.init.shared.b64 [%0], %1;" :: "r"(addr), "r"(cnt) : "memory")

#define MBAR_ARRIVE(addr) \
    asm volatile("mbarrier.arrive.shared.b64 _, [%0];" :: "r"(addr) : "memory")

#define CP_ASYNC_MBAR_ARRIVE(addr) \
    asm volatile("cp.async.mbarrier.arrive.noinc.shared.b64 [%0];" :: "r"(addr) : "memory")

#define MBAR_WAIT(addr, ph) do {                                                     \
    uint32_t _m = (addr), _p = (uint32_t)(ph), _d;                                   \
    asm volatile("{ .reg .pred p; mbarrier.try_wait.parity.shared.b64 p, [%1], %2;"  \
                 " selp.b32 %0, 1, 0, p; }" : "=r"(_d) : "r"(_m), "r"(_p) : "memory");\
    while (!_d) {                                                                    \
        asm volatile("{ .reg .pred p; mbarrier.try_wait.parity.shared.b64 p, [%1], %2, 0x989680;" \
                     " selp.b32 %0, 1, 0, p; }" : "=r"(_d) : "r"(_m), "r"(_p) : "memory");        \
    }                                                                                \
} while (0)

#define LDSM_X4(r0, r1, r2, r3, addr)                                        \
    asm volatile("ldmatrix.sync.aligned.m8n8.x4.shared.b16 {%0,%1,%2,%3}, [%4];" \
                 : "=r"(r0), "=r"(r1), "=r"(r2), "=r"(r3) : "r"(addr))

#define MMA_F16(d, a, b0, b1)                                                \
    asm volatile(                                                            \
        "mma.sync.aligned.m16n8k16.row.col.f32.f16.f16.f32 "                 \
        "{%0,%1,%2,%3}, {%4,%5,%6,%7}, {%8,%9}, {%0,%1,%2,%3};"              \
        : "+f"((d)[0]), "+f"((d)[1]), "+f"((d)[2]), "+f"((d)[3])             \
        : "r"((a)[0]), "r"((a)[1]), "r"((a)[2]), "r"((a)[3]),                \
          "r"(b0), "r"(b1))

// f16 accumulator variant: D/C are 2 packed half2 regs
#define MMA_F16A(d, a, b0, b1)                                               \
    asm volatile(                                                            \
        "mma.sync.aligned.m16n8k16.row.col.f16.f16.f16.f16 "                 \
        "{%0,%1}, {%2,%3,%4,%5}, {%6,%7}, {%0,%1};"                          \
        : "+r"((d)[0]), "+r"((d)[1])                                         \
        : "r"((a)[0]), "r"((a)[1]), "r"((a)[2]), "r"((a)[3]),                \
          "r"(b0), "r"(b1))

// ================= GEMM1: S = Fh @ Fh^T (f16 accum), symmetric triangle =================
// 16 warps (4x4 grid of 64x64 warp tiles), 256x256 CTA tile, 1 CTA/SM, 136 CTAs.
__global__ __launch_bounds__(THR1, 1) void gemm1_sym(const __half* __restrict__ F,
                                                     __half* __restrict__ S) {
    // decode linear upper-triangle index
    int t = blockIdx.x, by = 0;
    while (t >= NTILE1 - by) {
        t -= NTILE1 - by;
        by++;
    }
    const int bx = by + t;

    extern __shared__ char smem[];
    const uint32_t sb = smem_u32(smem);
    const int tid = threadIdx.x;
    const int wid = tid >> 5;
    const int lane = tid & 31;
    const int q = lane >> 2, r = lane & 3;
    const int wm = wid & 3;   // 4 warp rows x 64
    const int wn = wid >> 2;  // 4 warp cols x 64
    const int rowBase = by * BM1;
    const int colBase = bx * BM1;

#define FULL1(s) (sb + SMEM1_BAR + (s) * 8)
#define FREE1(s) (sb + SMEM1_BAR + 24 + (s) * 8)

    if (tid == 0) {
#pragma unroll
        for (int s = 0; s < STAGES; s++) {
            MBAR_INIT(FULL1(s), THR1);
            MBAR_INIT(FREE1(s), THR1);
        }
    }
    __syncthreads();

    // cp.async: per operand 256 rows x 128B = 2048 chunks; 4/thread/operand
    const int ldRow = tid >> 3;          // 0..63, +64 steps
    const int ldC = (tid & 7) * 16;
    const char* Ag = (const char*)F + ((size_t)(rowBase + ldRow) * NN) * 2 + ldC;
    const char* Bg = (const char*)F + ((size_t)(colBase + ldRow) * NN) * 2 + ldC;
    const size_t GROW = (size_t)64 * NN * 2;

    // ldmatrix lane mapping
    const int ml = lane >> 3;
    const int lrow = (ml & 1) * 8 + (lane & 7);
    const int lk = (ml >> 1) * 16;
    const uint32_t aoff = (uint32_t)((wm * 64 + lrow) * LDB + lk);
    const uint32_t boff = (uint32_t)(ASTG1 + (wn * 64 + lrow) * LDB + lk);

    uint32_t c[4][8][2];  // f16x2 accumulators: 64 regs
#pragma unroll
    for (int i = 0; i < 4; i++)
#pragma unroll
        for (int j = 0; j < 8; j++) c[i][j][0] = c[i][j][1] = 0u;

#define LOADSTAGE1(sidx)                                                           \
    do {                                                                           \
        const uint32_t s_b = sb + (sidx) * STG1;                                   \
        _Pragma("unroll") for (int l = 0; l < 4; l++) {                            \
            CP_ASYNC16(s_b + (ldRow + l * 64) * LDB + ldC, Ag + l * GROW);         \
            CP_ASYNC16(s_b + ASTG1 + (ldRow + l * 64) * LDB + ldC, Bg + l * GROW); \
        }                                                                          \
        CP_ASYNC_MBAR_ARRIVE(FULL1(sidx));                                         \
        Ag += 128;                                                                 \
        Bg += 128;                                                                 \
    } while (0)

#define COMPUTE1(sidx)                                                             \
    do {                                                                           \
        const uint32_t abase = sb + (sidx) * STG1 + aoff;                          \
        const uint32_t bbase = sb + (sidx) * STG1 + boff;                          \
        _Pragma("unroll") for (int ks = 0; ks < 4; ks++) {                         \
            uint32_t a[4][4], b[4][4];                                             \
            _Pragma("unroll") for (int im = 0; im < 4; im++)                       \
                LDSM_X4(a[im][0], a[im][1], a[im][2], a[im][3],                    \
                        abase + im * (16 * LDB) + ks * 32);                        \
            _Pragma("unroll") for (int jn = 0; jn < 4; jn++)                       \
                LDSM_X4(b[jn][0], b[jn][1], b[jn][2], b[jn][3],                    \
                        bbase + jn * (16 * LDB) + ks * 32);                        \
            _Pragma("unroll") for (int im = 0; im < 4; im++)                       \
                _Pragma("unroll") for (int n8 = 0; n8 < 8; n8++) {                 \
                    const int jn = n8 >> 1, o = n8 & 1;                            \
                    MMA_F16A(c[im][n8], a[im], b[jn][o], b[jn][2 + o]);            \
                }                                                                  \
        }                                                                          \
        MBAR_ARRIVE(FREE1(sidx));                                                  \
    } while (0)

    LOADSTAGE1(0);
    LOADSTAGE1(1);

    int pg = 0;
    for (int g = 0; g < 21; g++) {
        MBAR_WAIT(FULL1(0), pg);
        COMPUTE1(0);
        if (g > 0) MBAR_WAIT(FREE1(2), pg ^ 1);
        LOADSTAGE1(2);
        MBAR_WAIT(FULL1(1), pg);
        COMPUTE1(1);
        MBAR_WAIT(FREE1(0), pg);
        LOADSTAGE1(0);
        MBAR_WAIT(FULL1(2), pg);
        COMPUTE1(2);
        if (g < 20) {
            MBAR_WAIT(FREE1(1), pg);
            LOADSTAGE1(1);
        }
        pg ^= 1;
    }
    MBAR_WAIT(FULL1(0), pg);
    COMPUTE1(0);

    // direct write (accums are already the f16 logits; scale folded into Fh)
#pragma unroll
    for (int im = 0; im < 4; im++) {
        const int row0 = rowBase + wm * 64 + im * 16 + q;
#pragma unroll
        for (int n8 = 0; n8 < 8; n8++) {
            const int col = colBase + wn * 64 + n8 * 8 + 2 * r;
            *reinterpret_cast<uint32_t*>(S + (size_t)row0 * NN + col) = c[im][n8][0];
            *reinterpret_cast<uint32_t*>(S + (size_t)(row0 + 8) * NN + col) = c[im][n8][1];
        }
    }

    // mirror (transpose) for off-diagonal tiles
    if (by != bx) {
        __syncthreads();  // pipeline smem free -> transpose buffer
        __half* T = reinterpret_cast<__half*>(smem);
#pragma unroll
        for (int im = 0; im < 4; im++) {
            const int rl = wm * 64 + im * 16 + q;
#pragma unroll
            for (int n8 = 0; n8 < 8; n8++) {
                const int cl = wn * 64 + n8 * 8 + 2 * r;
                *reinterpret_cast<uint32_t*>(T + rl * TS1 + cl) = c[im][n8][0];
                *reinterpret_cast<uint32_t*>(T + (rl + 8) * TS1 + cl) = c[im][n8][1];
            }
        }
        __syncthreads();
        __half* Cb = S + (size_t)colBase * NN + rowBase;
#pragma unroll
        for (int it = 0; it < 16; it++) {
            const int r_t = it * 16 + wid;
            __half* dst = Cb + (size_t)r_t * NN;
#pragma unroll
            for (int j = 0; j < 8; j++) {
                const int c_t = lane + 32 * j;
                dst[c_t] = T[c_t * TS1 + r_t];  // 129-word stride -> conflict-free
            }
        }
    }
}

// ================= GEMM2: out = P @ Fh^T (fp32 accum) — R13/R14 winner unchanged =================
__global__ __launch_bounds__(THREADS, 2) void gemm2_f16(const __half* __restrict__ A,
                                                        const __half* __restrict__ B,
                                                        float* __restrict__ C) {
    extern __shared__ char smem[];
    const uint32_t sb = smem_u32(smem);
    const int tid = threadIdx.x;
    const int wid = tid >> 5;
    const int lane = tid & 31;
    const int q = lane >> 2, r = lane & 3;
    const int wm = wid & 1;
    const int wn = wid >> 1;
    const int rowBase = blockIdx.y * BM;
    const int colBase = blockIdx.x * BN;

#define FULLB(s) (sb + SMEM_BAR + (s) * 8)
#define FREEB(s) (sb + SMEM_BAR + 24 + (s) * 8)

    if (tid == 0) {
#pragma unroll
        for (int s = 0; s < STAGES; s++) {
            MBAR_INIT(FULLB(s), THREADS);
            MBAR_INIT(FREEB(s), THREADS);
        }
    }
    __syncthreads();

    const int ldRow = tid >> 3;
    const int ldC = (tid & 7) * 16;
    const char* Ag = (const char*)A + ((size_t)(rowBase + ldRow) * NN) * 2 + ldC;
    const char* Bg = (const char*)B + ((size_t)(colBase + ldRow) * NN) * 2 + ldC;
    const size_t GROW = (size_t)32 * NN * 2;

    const int ml = lane >> 3;
    const int lrow = (ml & 1) * 8 + (lane & 7);
    const int lk = (ml >> 1) * 16;
    const uint32_t aoff = (uint32_t)((wm * 64 + lrow) * LDB + lk);
    const uint32_t boff = (uint32_t)(ASTG + (wn * 32 + lrow) * LDB + lk);

    float c[4][4][4];
#pragma unroll
    for (int i = 0; i < 4; i++)
#pragma unroll
        for (int j = 0; j < 4; j++)
#pragma unroll
            for (int e = 0; e < 4; e++) c[i][j][e] = 0.f;

#define LOADSTAGE(sidx)                                                            \
    do {                                                                           \
        const uint32_t s_b = sb + (sidx) * STG;                                    \
        _Pragma("unroll") for (int l = 0; l < 4; l++) {                            \
            CP_ASYNC16(s_b + (ldRow + l * 32) * LDB + ldC, Ag + l * GROW);         \
            CP_ASYNC16(s_b + ASTG + (ldRow + l * 32) * LDB + ldC, Bg + l * GROW);  \
        }                                                                          \
        CP_ASYNC_MBAR_ARRIVE(FULLB(sidx));                                         \
        Ag += 128;                                                                 \
        Bg += 128;                                                                 \
    } while (0)

#define COMPUTE(sidx)                                                              \
    do {                                                                           \
        const uint32_t abase = sb + (sidx) * STG + aoff;                           \
        const uint32_t bbase = sb + (sidx) * STG + boff;                           \
        uint32_t a[2][4][4], b[2][2][4];                                           \
        _Pragma("unroll") for (int im = 0; im < 4; im++)                           \
            LDSM_X4(a[0][im][0], a[0][im][1], a[0][im][2], a[0][im][3],            \
                    abase + im * (16 * LDB));                                      \
        _Pragma("unroll") for (int jn = 0; jn < 2; jn++)                           \
            LDSM_X4(b[0][jn][0], b[0][jn][1], b[0][jn][2], b[0][jn][3],            \
                    bbase + jn * (16 * LDB));                                      \
        _Pragma("unroll") for (int ks = 0; ks < 4; ks++) {                         \
            const int cur = ks & 1;                                                \
            if (ks < 3) {                                                          \
                _Pragma("unroll") for (int im = 0; im < 4; im++)                   \
                    LDSM_X4(a[cur ^ 1][im][0], a[cur ^ 1][im][1],                  \
                            a[cur ^ 1][im][2], a[cur ^ 1][im][3],                  \
                            abase + im * (16 * LDB) + (ks + 1) * 32);              \
                _Pragma("unroll") for (int jn = 0; jn < 2; jn++)                   \
                    LDSM_X4(b[cur ^ 1][jn][0], b[cur ^ 1][jn][1],                  \
                            b[cur ^ 1][jn][2], b[cur ^ 1][jn][3],                  \
                            bbase + jn * (16 * LDB) + (ks + 1) * 32);              \
            }                                                                      \
            _Pragma("unroll") for (int im = 0; im < 4; im++)                       \
                _Pragma("unroll") for (int in_ = 0; in_ < 4; in_++) {              \
                    const int jn = in_ >> 1, o = in_ & 1;                          \
                    MMA_F16(c[im][in_], a[cur][im], b[cur][jn][o], b[cur][jn][2 + o]); \
                }                                                                  \
        }                                                                          \
        MBAR_ARRIVE(FREEB(sidx));                                                  \
    } while (0)

    LOADSTAGE(0);
    LOADSTAGE(1);

    int pg = 0;
    for (int g = 0; g < 21; g++) {
        MBAR_WAIT(FULLB(0), pg);
        COMPUTE(0);
        if (g > 0) MBAR_WAIT(FREEB(2), pg ^ 1);
        LOADSTAGE(2);
        MBAR_WAIT(FULLB(1), pg);
        COMPUTE(1);
        MBAR_WAIT(FREEB(0), pg);
        LOADSTAGE(0);
        MBAR_WAIT(FULLB(2), pg);
        COMPUTE(2);
        if (g < 20) {
            MBAR_WAIT(FREEB(1), pg);
            LOADSTAGE(1);
        }
        pg ^= 1;
    }
    MBAR_WAIT(FULLB(0), pg);
    COMPUTE(0);

#pragma unroll
    for (int im = 0; im < 4; im++) {
        const int row0 = rowBase + wm * 64 + im * 16 + q;
#pragma unroll
        for (int in_ = 0; in_ < 4; in_++) {
            const int col = colBase + wn * 32 + in_ * 8 + 2 * r;
            float2 v0 = make_float2(c[im][in_][0], c[im][in_][1]);
            float2 v1 = make_float2(c[im][in_][2], c[im][in_][3]);
            *reinterpret_cast<float2*>(C + (size_t)row0 * NN + col) = v0;
            *reinterpret_cast<float2*>(C + (size_t)(row0 + 8) * NN + col) = v1;
        }
    }
}

// ---------------- prep: Fh = feats / 64 in f16 (folds both GEMM scales, exact pow2) --------
__global__ __launch_bounds__(256) void prep_feats(const float* __restrict__ in,
                                                  __half* __restrict__ out) {
    size_t i = ((size_t)blockIdx.x * 256 + threadIdx.x) * 8;
    float4 v0 = *reinterpret_cast<const float4*>(in + i);
    float4 v1 = *reinterpret_cast<const float4*>(in + i + 4);
    const float s = 0.015625f;  // 1/64
    __half2 h[4];
    h[0] = __floats2half2_rn(v0.x * s, v0.y * s);
    h[1] = __floats2half2_rn(v0.z * s, v0.w * s);
    h[2] = __floats2half2_rn(v1.x * s, v1.y * s);
    h[3] = __floats2half2_rn(v1.z * s, v1.w * s);
    *reinterpret_cast<uint4*>(out + i) = *reinterpret_cast<uint4*>(h);
}

// ---------------- row softmax, register-resident, diag masked, f16 in-place ----------------
__global__ __launch_bounds__(256) void softmax_rows(__half* __restrict__ S) {
    __shared__ float red[8];
    const int ri = blockIdx.x;
    const int t = threadIdx.x;
    const int wid = t >> 5, lane = t & 31;
    uint4* rp = reinterpret_cast<uint4*>(S + (size_t)ri * NN);

    uint4 v0 = rp[t];
    uint4 v1 = rp[t + 256];
    float val[16];
    {
        const __half2* h0 = reinterpret_cast<const __half2*>(&v0);
        const __half2* h1 = reinterpret_cast<const __half2*>(&v1);
#pragma unroll
        for (int k = 0; k < 4; k++) {
            float2 f0 = __half22float2(h0[k]);
            float2 f1 = __half22float2(h1[k]);
            val[2 * k] = f0.x;
            val[2 * k + 1] = f0.y;
            val[8 + 2 * k] = f1.x;
            val[8 + 2 * k + 1] = f1.y;
        }
    }
    const int b0 = 8 * t, b1 = 2048 + 8 * t;
    if (ri >= b0 && ri < b0 + 8) val[ri - b0] = -3.4e38f;
    if (ri >= b1 && ri < b1 + 8) val[8 + ri - b1] = -3.4e38f;

    float m = val[0];
#pragma unroll
    for (int k = 1; k < 16; k++) m = fmaxf(m, val[k]);
#pragma unroll
    for (int o = 16; o > 0; o >>= 1) m = fmaxf(m, __shfl_xor_sync(0xFFFFFFFF, m, o));
    if (lane == 0) red[wid] = m;
    __syncthreads();
    {
        float x = red[lane & 7];
#pragma unroll
        for (int o = 4; o > 0; o >>= 1) x = fmaxf(x, __shfl_xor_sync(0xFFFFFFFF, x, o));
        m = x;
    }
    __syncthreads();

    float e[16];
    float s = 0.f;
#pragma unroll
    for (int k = 0; k < 16; k++) {
        e[k] = __expf(val[k] - m);
        s += e[k];
    }
#pragma unroll
    for (int o = 16; o > 0; o >>= 1) s += __shfl_xor_sync(0xFFFFFFFF, s, o);
    if (lane == 0) red[wid] = s;
    __syncthreads();
    {
        float x = red[lane & 7];
#pragma unroll
        for (int o = 4; o > 0; o >>= 1) x += __shfl_xor_sync(0xFFFFFFFF, x, o);
        s = x;
    }
    const float inv = 1.f / s;

    {
        __half2* h0 = reinterpret_cast<__half2*>(&v0);
        __half2* h1 = reinterpret_cast<__half2*>(&v1);
#pragma unroll
        for (int k = 0; k < 4; k++) {
            h0[k] = __floats2half2_rn(e[2 * k] * inv, e[2 * k + 1] * inv);
            h1[k] = __floats2half2_rn(e[8 + 2 * k] * inv, e[8 + 2 * k + 1] * inv);
        }
    }
    rp[t] = v0;
    rp[t + 256] = v1;
}

extern "C" void kernel_launch(void* const* d_in, const int* in_sizes, int n_in,
                              void* d_out, int out_size) {
    const float* feats = (const float*)d_in[0];
    float* out = (float*)d_out;

    void *sp, *fp;
    cudaGetSymbolAddress(&sp, g_Sh);
    cudaGetSymbolAddress(&fp, g_Fh);
    __half* Sh = (__half*)sp;
    __half* Fh = (__half*)fp;

    cudaFuncSetAttribute(gemm1_sym, cudaFuncAttributeMaxDynamicSharedMemorySize, SMEM1_TOTAL);
    cudaFuncSetAttribute(gemm2_f16, cudaFuncAttributeMaxDynamicSharedMemorySize, SMEM_TOTAL);

    // Fh = feats / 64  (x in the reference)
    prep_feats<<<(NN * NN) / 2048, 256>>>(feats, Fh);

    // S = Fh @ Fh^T (f16 accum, 136-CTA single-wave triangle + mirror)
    gemm1_sym<<<NTRI1, THR1, SMEM1_TOTAL>>>(Fh, Sh);
    // P = softmax(S), diag masked, in-place f16
    softmax_rows<<<NN, 256>>>(Sh);
    // out = P @ Fh^T (fp32 accum/out)
    dim3 grid2(NN / BN, NN / BM);  // (32, 32)
    gemm2_f16<<<grid2, THREADS, SMEM_TOTAL>>>(Sh, Fh, out);
}